// round 2
// baseline (speedup 1.0000x reference)
#include <cuda_runtime.h>

// LSTM: B=4096, T=256, F=18, H=64 (4H=256 gates i,f,g,o), classifier O=15.
// 128 CTAs x 256 threads; CTA owns 32 batch rows for the whole sequence.
// Thread = 2 rows x 8 gate-pairs. Packed f32x2 FMA; double-buffered act tiles,
// one barrier per timestep.

#define T_LEN 256
#define F_IN  18
#define H_DIM 64
#define G_DIM 256
#define O_DIM 15
#define ROWS  32
#define NTHR  256
#define NCTA  128

typedef unsigned long long u64;

#define HSTRIDE 66            // u64 per h row (64 data + 2 pad for bank skew)

// ---- shared memory layout (bytes) ----
#define SM_WT    0                          // float Wt[82][256]          = 83968
#define SM_HA    83968                      // u64 hact[2][32][66]        = 33792
#define SM_XA    (SM_HA + 33792)            // u64 xact[2][32][18]        = 9216
#define SM_BS    (SM_XA + 9216)             // float bs[256]              = 1024
#define SM_WCLS  (SM_BS + 1024)             // float wcls[15*64]          = 3840
#define SM_BCLS  (SM_WCLS + 3840)           // float bcls[16]             = 64
#define SM_TOTAL (SM_BCLS + 64)             // 131904

__device__ __forceinline__ u64 pack2(float x, float y) {
    u64 r; asm("mov.b64 %0, {%1, %2};" : "=l"(r) : "f"(x), "f"(y)); return r;
}
__device__ __forceinline__ void unpack2(u64 v, float& x, float& y) {
    asm("mov.b64 {%0, %1}, %2;" : "=f"(x), "=f"(y) : "l"(v));
}
__device__ __forceinline__ void fma2(u64& d, u64 a, u64 b) {
    asm("fma.rn.f32x2 %0, %1, %2, %3;" : "=l"(d) : "l"(a), "l"(b), "l"(d));
}

// accurate fast sigmoid/tanh (MUFU.EX2 + MUFU.RCP, ~1e-6 rel err, inf-safe)
__device__ __forceinline__ float sig_(float x) {
    float e = __expf(-x);
    return __fdividef(1.0f, 1.0f + e);
}
__device__ __forceinline__ float tanh_(float x) {
    float e = __expf(2.0f * x);
    return 1.0f - __fdividef(2.0f, e + 1.0f);
}

__global__ void __launch_bounds__(NTHR, 1) lstm_kernel(
    const float* __restrict__ X,      // [B,T,F]
    const float* __restrict__ W_ih,   // [4H,F]
    const float* __restrict__ W_hh,   // [4H,H]
    const float* __restrict__ b_ih,   // [4H]
    const float* __restrict__ b_hh,   // [4H]
    const float* __restrict__ W_cls,  // [O,H]
    const float* __restrict__ b_cls,  // [O]
    float* __restrict__ out)          // [B,O]
{
    extern __shared__ char sm[];
    float* Wt   = (float*)(sm + SM_WT);    // Wt[k][g]: k<64 -> W_hh[g][k]; k=64+f -> W_ih[g][f]
    float* bs   = (float*)(sm + SM_BS);
    float* wcls = (float*)(sm + SM_WCLS);
    float* bcl  = (float*)(sm + SM_BCLS);

    const int tid = threadIdx.x;
    const int tg  = tid & 15;    // gate group: owns gates 64q + 32p + 2tg + {0,1}
    const int tr  = tid >> 4;    // row group 0..15: rows 2tr, 2tr+1
    const int row0 = blockIdx.x * ROWS;

    // ---- one-time setup ----
    for (int i = tid; i < H_DIM * G_DIM; i += NTHR) {
        int k = i >> 8, g = i & 255;
        Wt[k * G_DIM + g] = W_hh[g * H_DIM + k];
    }
    for (int i = tid; i < F_IN * G_DIM; i += NTHR) {
        int f = i >> 8, g = i & 255;
        Wt[(H_DIM + f) * G_DIM + g] = W_ih[g * F_IN + f];
    }
    for (int g = tid; g < G_DIM; g += NTHR) bs[g] = b_ih[g] + b_hh[g];
    for (int i = tid; i < O_DIM * H_DIM; i += NTHR) wcls[i] = W_cls[i];
    if (tid < O_DIM) bcl[tid] = b_cls[tid];

    // zero hact[0]
    {
        u64* h0 = (u64*)(sm + SM_HA);
        for (int i = tid; i < ROWS * HSTRIDE; i += NTHR) h0[i] = 0ull;
    }

    // X prefetch mapping: element e = tid + 256*m of the 32x18 step tile
    int pb[3], pf[3]; bool pv[3];
#pragma unroll
    for (int m = 0; m < 3; m++) {
        int e = tid + NTHR * m;
        pv[m] = (e < ROWS * F_IN);
        int b = e / F_IN;
        pb[m] = b;
        pf[m] = e - b * F_IN;
    }
    const float* Xbase = X + (long long)row0 * T_LEN * F_IN;

    // stage x(0) into xact[0]
    {
        u64* x0 = (u64*)(sm + SM_XA);
        float xv[3];
#pragma unroll
        for (int m = 0; m < 3; m++)
            xv[m] = pv[m] ? Xbase[(long long)pb[m] * (T_LEN * F_IN) + pf[m]] : 0.0f;
#pragma unroll
        for (int m = 0; m < 3; m++)
            if (pv[m]) x0[pb[m] * F_IN + pf[m]] = pack2(xv[m], xv[m]);
    }

    // gate-pair biases kept in registers
    u64 biasv[4][2];
#pragma unroll
    for (int q = 0; q < 4; q++)
#pragma unroll
        for (int p = 0; p < 2; p++)
            biasv[q][p] = ((const u64*)bs)[q * 32 + p * 16 + tg];

    float creg[2][4];
#pragma unroll
    for (int r = 0; r < 2; r++)
#pragma unroll
        for (int c = 0; c < 4; c++) creg[r][c] = 0.0f;

    const u64* wt2 = (const u64*)Wt;   // row k = 128 u64
    int buf = 0;

    // ================= time loop =================
    for (int t = 0; t < T_LEN; ++t) {
        __syncthreads();   // publishes into buf (from t-1) visible; buf^1 free

        const u64* hb = (const u64*)(sm + SM_HA + buf * (ROWS * HSTRIDE * 8));
        const u64* xb = (const u64*)(sm + SM_XA + buf * (ROWS * F_IN * 8));
        u64* hb2 = (u64*)(sm + SM_HA + (buf ^ 1) * (ROWS * HSTRIDE * 8));
        u64* xb2 = (u64*)(sm + SM_XA + (buf ^ 1) * (ROWS * F_IN * 8));

        // prefetch x(t+1) under the compute
        float xp[3];
        if (t + 1 < T_LEN) {
#pragma unroll
            for (int m = 0; m < 3; m++)
                xp[m] = pv[m]
                    ? Xbase[(long long)pb[m] * (T_LEN * F_IN) + (t + 1) * F_IN + pf[m]]
                    : 0.0f;
        }

        u64 acc[2][4][2];
#pragma unroll
        for (int r = 0; r < 2; r++)
#pragma unroll
            for (int q = 0; q < 4; q++)
#pragma unroll
                for (int p = 0; p < 2; p++) acc[r][q][p] = biasv[q][p];

        // ---- x-part: k = 64..81 ----
        const int xab = 2 * tr * F_IN;
#pragma unroll 3
        for (int f = 0; f < F_IN; f++) {
            u64 a0 = xb[xab + f];
            u64 a1 = xb[xab + F_IN + f];
            const u64* wrow = wt2 + (H_DIM + f) * 128 + tg;
#pragma unroll
            for (int q = 0; q < 4; q++)
#pragma unroll
                for (int p = 0; p < 2; p++) {
                    u64 w = wrow[q * 32 + p * 16];
                    fma2(acc[0][q][p], a0, w);
                    fma2(acc[1][q][p], a1, w);
                }
        }

        // ---- h-part: k = 0..63 ----
        const int hab = 2 * tr * HSTRIDE;
#pragma unroll 4
        for (int k = 0; k < H_DIM; k++) {
            u64 a0 = hb[hab + k];
            u64 a1 = hb[hab + HSTRIDE + k];
            const u64* wrow = wt2 + k * 128 + tg;
#pragma unroll
            for (int q = 0; q < 4; q++)
#pragma unroll
                for (int p = 0; p < 2; p++) {
                    u64 w = wrow[q * 32 + p * 16];
                    fma2(acc[0][q][p], a0, w);
                    fma2(acc[1][q][p], a1, w);
                }
        }

        // ---- cell update + publish h(t) into buf^1 ----
#pragma unroll
        for (int r = 0; r < 2; r++) {
#pragma unroll
            for (int p = 0; p < 2; p++) {
                float i0, i1, f0, f1, g0, g1, o0, o1;
                unpack2(acc[r][0][p], i0, i1);
                unpack2(acc[r][1][p], f0, f1);
                unpack2(acc[r][2][p], g0, g1);
                unpack2(acc[r][3][p], o0, o1);
                float c0 = creg[r][2 * p], c1 = creg[r][2 * p + 1];
                c0 = sig_(f0) * c0 + sig_(i0) * tanh_(g0);
                c1 = sig_(f1) * c1 + sig_(i1) * tanh_(g1);
                creg[r][2 * p]     = c0;
                creg[r][2 * p + 1] = c1;
                float h0 = sig_(o0) * tanh_(c0);
                float h1 = sig_(o1) * tanh_(c1);
                int base = (2 * tr + r) * HSTRIDE + 32 * p + 2 * tg;
                hb2[base]     = pack2(h0, h0);
                hb2[base + 1] = pack2(h1, h1);
            }
        }

        // publish x(t+1)
        if (t + 1 < T_LEN) {
#pragma unroll
            for (int m = 0; m < 3; m++)
                if (pv[m]) xb2[pb[m] * F_IN + pf[m]] = pack2(xp[m], xp[m]);
        }

        buf ^= 1;
    }

    // ---- classifier head on final h (published into hact[buf]) ----
    __syncthreads();
    const float* hf = (const float*)(sm + SM_HA + buf * (ROWS * HSTRIDE * 8));

    for (int e = tid; e < ROWS * O_DIM; e += NTHR) {
        int b = e / O_DIM, o = e - b * O_DIM;
        float s = bcl[o];
#pragma unroll
        for (int j = 0; j < H_DIM; j++)
            s += hf[(b * HSTRIDE + j) * 2] * wcls[o * H_DIM + j];
        out[(long long)(row0 + b) * O_DIM + o] = s;
    }
}

extern "C" void kernel_launch(void* const* d_in, const int* in_sizes, int n_in,
                              void* d_out, int out_size)
{
    const float* X     = (const float*)d_in[0];
    const float* W_ih  = (const float*)d_in[1];
    const float* W_hh  = (const float*)d_in[2];
    const float* b_ih  = (const float*)d_in[3];
    const float* b_hh  = (const float*)d_in[4];
    const float* W_cls = (const float*)d_in[5];
    const float* b_cls = (const float*)d_in[6];

    cudaFuncSetAttribute(lstm_kernel,
                         cudaFuncAttributeMaxDynamicSharedMemorySize, SM_TOTAL);
    lstm_kernel<<<NCTA, NTHR, SM_TOTAL>>>(X, W_ih, W_hh, b_ih, b_hh,
                                          W_cls, b_cls, (float*)d_out);
}

// round 4
// speedup vs baseline: 1.2132x; 1.2132x over previous
#include <cuda_runtime.h>

// LSTM: B=4096, T=256, F=18, H=64 (4H=256 gates i,f,g,o), classifier O=15.
// 128 CTAs x 256 threads; CTA owns 32 batch rows for the whole sequence.
// k-split warp specialization: warps 0-3 (group A) reduce k=0..40,
// warps 4-7 (group B) reduce k=41..81; A stores partials to smem, B combines,
// runs the nonlinear cell update, and publishes h. Packed f32x2 FMA throughout.

#define T_LEN 256
#define F_IN  18
#define H_DIM 64
#define G_DIM 256
#define O_DIM 15
#define ROWS  32
#define NTHR  256
#define NCTA  128
#define GK    32      // h-k steps per group
#define GF    9       // x-f steps per group

typedef unsigned long long u64;

#define HSTRIDE 66    // u64 per h row (64 data + 2 pad)

// ---- shared memory layout (bytes) ----
#define SM_WT    0                           // float Wt[82][256]      = 83968
#define SM_H     83968                       // u64 h[32][66]          = 16896
#define SM_X     (SM_H + 16896)              // u64 x[2][32][18]       = 9216
#define SM_RED   (SM_X + 9216)               // u64 red[32][128]       = 32768
#define SM_BS    (SM_RED + 32768)            // float bs[256]          = 1024
#define SM_WCLS  (SM_BS + 1024)              // float wcls[15*64]      = 3840
#define SM_BCLS  (SM_WCLS + 3840)            // float bcls[16]         = 64
#define SM_TOTAL (SM_BCLS + 64)              // 147776

__device__ __forceinline__ u64 pack2(float x, float y) {
    u64 r; asm("mov.b64 %0, {%1, %2};" : "=l"(r) : "f"(x), "f"(y)); return r;
}
__device__ __forceinline__ void unpack2(u64 v, float& x, float& y) {
    asm("mov.b64 {%0, %1}, %2;" : "=f"(x), "=f"(y) : "l"(v));
}
__device__ __forceinline__ void fma2(u64& d, u64 a, u64 b) {
    asm("fma.rn.f32x2 %0, %1, %2, %3;" : "=l"(d) : "l"(a), "l"(b), "l"(d));
}
__device__ __forceinline__ void add2(u64& d, u64 a) {
    asm("add.rn.f32x2 %0, %1, %2;" : "=l"(d) : "l"(d), "l"(a));
}

// accurate fast sigmoid/tanh (MUFU.EX2 + MUFU.RCP, ~1e-6 rel err, inf-safe)
__device__ __forceinline__ float sig_(float x) {
    float e = __expf(-x);
    return __fdividef(1.0f, 1.0f + e);
}
__device__ __forceinline__ float tanh_(float x) {
    float e = __expf(2.0f * x);
    return 1.0f - __fdividef(2.0f, e + 1.0f);
}

__global__ void __launch_bounds__(NTHR, 1) lstm_kernel(
    const float* __restrict__ X,      // [B,T,F]
    const float* __restrict__ W_ih,   // [4H,F]
    const float* __restrict__ W_hh,   // [4H,H]
    const float* __restrict__ b_ih,   // [4H]
    const float* __restrict__ b_hh,   // [4H]
    const float* __restrict__ W_cls,  // [O,H]
    const float* __restrict__ b_cls,  // [O]
    float* __restrict__ out)          // [B,O]
{
    extern __shared__ char sm[];
    float* Wt   = (float*)(sm + SM_WT);   // Wt[k][g]: k<64 -> W_hh[g][k]; k=64+f -> W_ih[g][f]
    u64*   hbuf = (u64*)  (sm + SM_H);
    u64*   red  = (u64*)  (sm + SM_RED);  // red[i][lane] = red[i*128 + lt]
    float* bs   = (float*)(sm + SM_BS);
    float* wcls = (float*)(sm + SM_WCLS);
    float* bcl  = (float*)(sm + SM_BCLS);

    const int tid  = threadIdx.x;
    const int lt   = tid & 127;
    const int gsel = tid >> 7;          // 0 = group A, 1 = group B
    const int tg   = tid & 15;          // gate group: gates 64q + 32p + 2tg + {0,1}
    const int tr   = (tid >> 4) & 7;    // row group: rows 4tr .. 4tr+3
    const int row0 = blockIdx.x * ROWS;

    // ---- one-time setup ----
    for (int i = tid; i < H_DIM * G_DIM; i += NTHR) {
        int k = i >> 8, g = i & 255;
        Wt[k * G_DIM + g] = W_hh[g * H_DIM + k];
    }
    for (int i = tid; i < F_IN * G_DIM; i += NTHR) {
        int f = i >> 8, g = i & 255;
        Wt[(H_DIM + f) * G_DIM + g] = W_ih[g * F_IN + f];
    }
    for (int g = tid; g < G_DIM; g += NTHR) bs[g] = b_ih[g] + b_hh[g];
    for (int i = tid; i < O_DIM * H_DIM; i += NTHR) wcls[i] = W_cls[i];
    if (tid < O_DIM) bcl[tid] = b_cls[tid];
    for (int i = tid; i < ROWS * HSTRIDE; i += NTHR) hbuf[i] = 0ull;  // h(-1)=0

    // X prefetch mapping over 128 lanes (group A stages x): 5 slots cover 32x18
    int pb[5], pf[5]; bool pv[5];
#pragma unroll
    for (int m = 0; m < 5; m++) {
        int e = lt + 128 * m;
        pv[m] = (e < ROWS * F_IN);
        int b = e / F_IN;
        pb[m] = b;
        pf[m] = e - b * F_IN;
    }
    const float* Xbase = X + (long long)row0 * T_LEN * F_IN;

    // stage x(0) into xbuf[0] (group A only)
    if (gsel == 0) {
        u64* x0 = (u64*)(sm + SM_X);
#pragma unroll
        for (int m = 0; m < 5; m++)
            if (pv[m]) {
                float v = Xbase[(long long)pb[m] * (T_LEN * F_IN) + pf[m]];
                x0[pb[m] * F_IN + pf[m]] = pack2(v, v);
            }
    }

    // gate-pair biases in registers (used by group B)
    u64 biasv[4][2];
#pragma unroll
    for (int q = 0; q < 4; q++)
#pragma unroll
        for (int p = 0; p < 2; p++)
            biasv[q][p] = ((const u64*)bs)[q * 32 + p * 16 + tg];

    float creg[4][4];   // cell state (group B owns it)
#pragma unroll
    for (int r = 0; r < 4; r++)
#pragma unroll
        for (int c = 0; c < 4; c++) creg[r][c] = 0.0f;

    const u64* wt2 = (const u64*)Wt;    // Wt row k = 128 u64
    const int hab = 4 * tr * HSTRIDE;
    const int xab = 4 * tr * F_IN;
    const int kh0 = gsel * GK;          // h-k start for this group
    const int xf0 = gsel * GF;          // x-f start for this group
    int buf = 0;

    // ================= time loop =================
    for (int t = 0; t < T_LEN; ++t) {
        __syncthreads();   // bar1: h(t-1), x(t) visible; red/xb^1 free

        const u64* xb  = (const u64*)(sm + SM_X) + buf * (ROWS * F_IN);
        u64*       xb2 = (u64*)(sm + SM_X) + (buf ^ 1) * (ROWS * F_IN);

        // group A: issue x(t+1) loads early (published after bar2)
        float xp[5];
        if (gsel == 0 && t + 1 < T_LEN) {
#pragma unroll
            for (int m = 0; m < 5; m++)
                xp[m] = pv[m]
                    ? Xbase[(long long)pb[m] * (T_LEN * F_IN) + (t + 1) * F_IN + pf[m]]
                    : 0.0f;
        }

        u64 acc[4][4][2];
#pragma unroll
        for (int r = 0; r < 4; r++)
#pragma unroll
            for (int q = 0; q < 4; q++)
#pragma unroll
                for (int p = 0; p < 2; p++)
                    acc[r][q][p] = gsel ? biasv[q][p] : 0ull;

        // ---- x-part: this group's 9 f's ----
#pragma unroll 3
        for (int ff = 0; ff < GF; ff++) {
            int f = xf0 + ff;
            u64 a0 = xb[xab + f];
            u64 a1 = xb[xab + F_IN + f];
            u64 a2 = xb[xab + 2 * F_IN + f];
            u64 a3 = xb[xab + 3 * F_IN + f];
            const u64* wrow = wt2 + (H_DIM + f) * 128 + tg;
#pragma unroll
            for (int q = 0; q < 4; q++)
#pragma unroll
                for (int p = 0; p < 2; p++) {
                    u64 w = wrow[q * 32 + p * 16];
                    fma2(acc[0][q][p], a0, w);
                    fma2(acc[1][q][p], a1, w);
                    fma2(acc[2][q][p], a2, w);
                    fma2(acc[3][q][p], a3, w);
                }
        }

        // ---- h-part: this group's 32 k's ----
#pragma unroll 4
        for (int kk = 0; kk < GK; kk++) {
            int k = kh0 + kk;
            u64 a0 = hbuf[hab + k];
            u64 a1 = hbuf[hab + HSTRIDE + k];
            u64 a2 = hbuf[hab + 2 * HSTRIDE + k];
            u64 a3 = hbuf[hab + 3 * HSTRIDE + k];
            const u64* wrow = wt2 + k * 128 + tg;
#pragma unroll
            for (int q = 0; q < 4; q++)
#pragma unroll
                for (int p = 0; p < 2; p++) {
                    u64 w = wrow[q * 32 + p * 16];
                    fma2(acc[0][q][p], a0, w);
                    fma2(acc[1][q][p], a1, w);
                    fma2(acc[2][q][p], a2, w);
                    fma2(acc[3][q][p], a3, w);
                }
        }

        // ---- group A publishes partials ----
        if (gsel == 0) {
            const u64* af = &acc[0][0][0];
#pragma unroll
            for (int i = 0; i < 32; i++) red[i * 128 + lt] = af[i];
        }
        __syncthreads();   // bar2: partials visible; k-loop readers of h/x done

        if (gsel == 0) {
            // publish x(t+1)
            if (t + 1 < T_LEN) {
#pragma unroll
                for (int m = 0; m < 5; m++)
                    if (pv[m]) xb2[pb[m] * F_IN + pf[m]] = pack2(xp[m], xp[m]);
            }
        } else {
            // combine partials
            u64* af = &acc[0][0][0];
#pragma unroll
            for (int i = 0; i < 32; i++) add2(af[i], red[i * 128 + lt]);

            // cell update + publish h(t)
#pragma unroll
            for (int r = 0; r < 4; r++) {
#pragma unroll
                for (int p = 0; p < 2; p++) {
                    float i0, i1, f0, f1, g0, g1, o0, o1;
                    unpack2(acc[r][0][p], i0, i1);
                    unpack2(acc[r][1][p], f0, f1);
                    unpack2(acc[r][2][p], g0, g1);
                    unpack2(acc[r][3][p], o0, o1);
                    float c0 = creg[r][2 * p], c1 = creg[r][2 * p + 1];
                    c0 = sig_(f0) * c0 + sig_(i0) * tanh_(g0);
                    c1 = sig_(f1) * c1 + sig_(i1) * tanh_(g1);
                    creg[r][2 * p]     = c0;
                    creg[r][2 * p + 1] = c1;
                    float h0 = sig_(o0) * tanh_(c0);
                    float h1 = sig_(o1) * tanh_(c1);
                    int base = (4 * tr + r) * HSTRIDE + 32 * p + 2 * tg;
                    hbuf[base]     = pack2(h0, h0);
                    hbuf[base + 1] = pack2(h1, h1);
                }
            }
        }

        buf ^= 1;
    }

    // ---- classifier head on final h ----
    __syncthreads();
    const float* hf = (const float*)hbuf;

    for (int e = tid; e < ROWS * O_DIM; e += NTHR) {
        int b = e / O_DIM, o = e - b * O_DIM;
        float s = bcl[o];
#pragma unroll
        for (int j = 0; j < H_DIM; j++)
            s += hf[(b * HSTRIDE + j) * 2] * wcls[o * H_DIM + j];
        out[(long long)(row0 + b) * O_DIM + o] = s;
    }
}

extern "C" void kernel_launch(void* const* d_in, const int* in_sizes, int n_in,
                              void* d_out, int out_size)
{
    const float* X     = (const float*)d_in[0];
    const float* W_ih  = (const float*)d_in[1];
    const float* W_hh  = (const float*)d_in[2];
    const float* b_ih  = (const float*)d_in[3];
    const float* b_hh  = (const float*)d_in[4];
    const float* W_cls = (const float*)d_in[5];
    const float* b_cls = (const float*)d_in[6];

    cudaFuncSetAttribute(lstm_kernel,
                         cudaFuncAttributeMaxDynamicSharedMemorySize, SM_TOTAL);
    lstm_kernel<<<NCTA, NTHR, SM_TOTAL>>>(X, W_ih, W_hh, b_ih, b_hh,
                                          W_cls, b_cls, (float*)d_out);
}